// round 1
// baseline (speedup 1.0000x reference)
#include <cuda_runtime.h>
#include <cuda_bf16.h>
#include <cstdint>

#define N_NODES 2048
#define EPS 0.01f
#define ROWS_PER_BLOCK 16
#define THREADS 256

__device__ int g_count;

__global__ void zero_kernel() {
    g_count = 0;
}

__global__ void __launch_bounds__(THREADS) count_kernel(
    const float* __restrict__ W, const float* __restrict__ pred)
{
    const int b = blockIdx.y;
    const int row0 = blockIdx.x * ROWS_PER_BLOCK;

    __shared__ float4 s_pred[N_NODES / 4];

    // cache pred[b] in shared (8 KB), float4 loads
    const float4* predb = (const float4*)(pred + (size_t)b * N_NODES);
    for (int i = threadIdx.x; i < N_NODES / 4; i += THREADS)
        s_pred[i] = predb[i];
    __syncthreads();

    // channel 1 of W for this batch: W[b,1,:,:]
    const float4* Wb = (const float4*)(W + ((size_t)b * 2 + 1) * (size_t)N_NODES * N_NODES);

    int cnt = 0;
    for (int r = 0; r < ROWS_PER_BLOCK; ++r) {
        const int row = row0 + r;
        const float pi = ((const float*)s_pred)[row];
        const float4* wrow = Wb + (size_t)row * (N_NODES / 4);
        #pragma unroll 4
        for (int c = threadIdx.x; c < N_NODES / 4; c += THREADS) {
            const float4 w  = wrow[c];
            const float4 pj = s_pred[c];
            cnt += (w.x == 1.0f) & (fabsf(pi - pj.x) < EPS);
            cnt += (w.y == 1.0f) & (fabsf(pi - pj.y) < EPS);
            cnt += (w.z == 1.0f) & (fabsf(pi - pj.z) < EPS);
            cnt += (w.w == 1.0f) & (fabsf(pi - pj.w) < EPS);
        }
    }

    // warp reduce
    #pragma unroll
    for (int o = 16; o > 0; o >>= 1)
        cnt += __shfl_xor_sync(0xffffffffu, cnt, o);

    __shared__ int warpsum[THREADS / 32];
    if ((threadIdx.x & 31) == 0)
        warpsum[threadIdx.x >> 5] = cnt;
    __syncthreads();

    if (threadIdx.x < THREADS / 32) {
        int v = warpsum[threadIdx.x];
        #pragma unroll
        for (int o = (THREADS / 64); o > 0; o >>= 1)
            v += __shfl_xor_sync(0xffu, v, o);
        if (threadIdx.x == 0)
            atomicAdd(&g_count, v);
    }
}

__global__ void finalize_kernel(float* __restrict__ out) {
    out[0] = (float)g_count;
}

extern "C" void kernel_launch(void* const* d_in, const int* in_sizes, int n_in,
                              void* d_out, int out_size)
{
    const float* W    = (const float*)d_in[0];
    const float* pred = (const float*)d_in[1];
    // d_in[2] (tgt) unused by the loss
    float* out = (float*)d_out;

    const int B = in_sizes[1] / N_NODES;  // pred has B*N elements

    zero_kernel<<<1, 1>>>();
    dim3 grid(N_NODES / ROWS_PER_BLOCK, B);
    count_kernel<<<grid, THREADS>>>(W, pred);
    finalize_kernel<<<1, 1>>>(out);
}